// round 10
// baseline (speedup 1.0000x reference)
#include <cuda_runtime.h>
#include <cuda_fp16.h>
#include <stdint.h>

// ---------------------------------------------------------------------------
// StyleGAN2 modulated 3x3 conv, NHWC, N=16 H=W=64 C=O=512
// Round 10: R7 config (CTA 128x128, warp 32x64, kc=64, 3 stages, 2 CTAs/SM,
//           single-product fp16) with __syncthreads replaced by per-stage
//           mbarriers (cp.async.mbarrier.arrive.noinc): warps no longer
//           phase-align per chunk, so LDSM bursts of some warps overlap the
//           MMA bursts of others.
// ---------------------------------------------------------------------------

#define NN 16
#define HH 64
#define WW 64
#define CC 512
#define OO 512
#define NWD 14

#define STAGE_BYTES 32768   // A 16K | B 16K
#define OFF_B  16384
#define NCHUNK 72           // 9 taps x 8 c-chunks (kc=64)

// ---- device scratch (allocation-free) --------------------------------------
__device__ float g_s[NN * CC];
__device__ float g_dmul[NN * OO];
__device__ float g_ssq[CC * OO];
__device__ __half g_xh[NN * HH * WW * CC];   // fp16(x*s)
__device__ __half g_wt[9 * OO * CC];         // fp16 w^T [tap][o][c]

// ---- helpers -----------------------------------------------------------------
static __device__ __forceinline__ uint32_t smem_u32(const void* p) {
    uint32_t a;
    asm("{ .reg .u64 t; cvta.to.shared.u64 t, %1; cvt.u32.u64 %0, t; }"
        : "=r"(a) : "l"(p));
    return a;
}

#define CP16(dst, src, sz)                                                   \
    asm volatile("cp.async.cg.shared.global [%0], [%1], 16, %2;"             \
                 :: "r"(dst), "l"(src), "r"(sz) : "memory")

#define MB_INIT(m, c)                                                        \
    asm volatile("mbarrier.init.shared.b64 [%0], %1;" :: "r"(m), "r"(c) : "memory")
#define MB_ARRIVE(m)                                                         \
    asm volatile("mbarrier.arrive.shared.b64 _, [%0];" :: "r"(m) : "memory")
#define CP_MB_ARRIVE(m)                                                      \
    asm volatile("cp.async.mbarrier.arrive.noinc.shared.b64 [%0];" :: "r"(m) : "memory")

#define MB_WAIT_PAR(mbar, parity) do {                                       \
    uint32_t _m = (uint32_t)(mbar);                                          \
    uint32_t _p = (uint32_t)(parity);                                        \
    uint32_t _done;                                                          \
    asm volatile("{ .reg .pred p;\n\t"                                       \
        "mbarrier.try_wait.parity.acquire.cta.shared::cta.b64 p, [%1], %2;\n\t" \
        "selp.b32 %0, 1, 0, p; }"                                            \
        : "=r"(_done) : "r"(_m), "r"(_p) : "memory");                        \
    if (!_done) {                                                            \
        asm volatile("{ .reg .pred P1;\n\t"                                  \
            "WL_%=:\n\t"                                                     \
            "mbarrier.try_wait.parity.acquire.cta.shared::cta.b64 P1, [%0], %1, 0x989680;\n\t" \
            "@P1 bra.uni WD_%=;\n\t"                                         \
            "bra.uni WL_%=;\n\t"                                             \
            "WD_%=: }"                                                       \
            :: "r"(_m), "r"(_p) : "memory");                                 \
    }                                                                        \
} while (0)

#define LDSM4(r, addr)                                                       \
    asm volatile("ldmatrix.sync.aligned.m8n8.x4.shared.b16 "                 \
                 "{%0,%1,%2,%3}, [%4];"                                      \
                 : "=r"((r)[0]), "=r"((r)[1]), "=r"((r)[2]), "=r"((r)[3])    \
                 : "r"(addr))

#define MMA2(d, a, b0, b1)                                                   \
    asm volatile("mma.sync.aligned.m16n8k16.row.col.f32.f16.f16.f32 "        \
                 "{%0,%1,%2,%3}, {%4,%5,%6,%7}, {%8,%9}, {%0,%1,%2,%3};"     \
                 : "+f"((d)[0]), "+f"((d)[1]), "+f"((d)[2]), "+f"((d)[3])    \
                 : "r"((a)[0]), "r"((a)[1]), "r"((a)[2]), "r"((a)[3]),       \
                   "r"(b0), "r"(b1))

// 128B rows, 8x16B chunks, XOR swizzle by row&7 (conflict-free ldmatrix)
#define SWZ128(row, ch) (((row) * 128) + ((((ch) ^ ((row) & 7))) << 4))

// ---- prep 1: style (blocks 0..15) + ssq (blocks 16..527) ----------------------
__global__ void prep1_kernel(const float* __restrict__ dlat,
                             const float* __restrict__ sw,
                             const float* __restrict__ sb,
                             const int*   __restrict__ lidx,
                             const float* __restrict__ weight)
{
    int bid = blockIdx.x;
    int t = threadIdx.x;
    if (bid < NN) {
        int n = bid;
        __shared__ float dl[CC];
        int li = *lidx;
        dl[t] = dlat[(n * NWD + li) * CC + t];
        __syncthreads();
        float acc = 0.f;
#pragma unroll 4
        for (int w = 0; w < CC; ++w)
            acc += dl[w] * sw[w * CC + t];
        g_s[n * CC + t] = acc * 0.044194173824159216f + sb[t];
    } else {
        int i = bid - NN;
        float acc = 0.f;
#pragma unroll
        for (int tp = 0; tp < 9; ++tp) {
            float v = weight[(tp * CC + i) * OO + t];
            acc += v * v;
        }
        g_ssq[i * OO + t] = acc;
    }
}

// ---- prep 2: dmul[n,o] ---------------------------------------------------------
__global__ void dmul_kernel()
{
    int n = blockIdx.x;
    int o = threadIdx.x;
    __shared__ float s2[CC];
    float sv = g_s[n * CC + o];
    s2[o] = sv * sv;
    __syncthreads();
    float acc = 0.f;
#pragma unroll 4
    for (int i = 0; i < CC; ++i)
        acc += s2[i] * g_ssq[i * OO + o];
    const float ws2 = 1.0f / 4608.0f;
    const float ws  = 0.014731391274719738f;
    g_dmul[n * OO + o] = ws * rsqrtf(ws2 * acc + 1e-8f);
}

// ---- prep 3: x*s -> fp16 (blocks < 32768) + w transpose fp16 (rest) -------------
__global__ void prep3_kernel(const float* __restrict__ x,
                             const float* __restrict__ weight)
{
    int bid = blockIdx.x;
    int tid = threadIdx.x;
    if (bid < 32768) {
        int t = bid * 256 + tid;
        int e = t * 4;
        int c = e & (CC - 1);
        int n = e >> 21;
        float4 v = *(const float4*)(x + e);
        float4 s = *(const float4*)(g_s + n * CC + c);
        __half h0 = __float2half_rn(v.x * s.x);
        __half h1 = __float2half_rn(v.y * s.y);
        __half h2 = __float2half_rn(v.z * s.z);
        __half h3 = __float2half_rn(v.w * s.w);
        uint2 ph;
        ph.x = (uint32_t)__half_as_ushort(h0) | ((uint32_t)__half_as_ushort(h1) << 16);
        ph.y = (uint32_t)__half_as_ushort(h2) | ((uint32_t)__half_as_ushort(h3) << 16);
        *(uint2*)(g_xh + e) = ph;
    } else {
        __shared__ float ts[32][33];
        int wb = bid - 32768;            // 0..2303
        int tap = wb >> 8;
        int rem = wb & 255;
        int o0 = (rem & 15) * 32;
        int c0 = (rem >> 4) * 32;
        int tx = tid & 31, ty = tid >> 5;
        for (int j = ty; j < 32; j += 8)
            ts[j][tx] = weight[(tap * CC + c0 + j) * OO + o0 + tx];
        __syncthreads();
        for (int j = ty; j < 32; j += 8) {
            float v = ts[tx][j];
            int oi = (tap * OO + o0 + j) * CC + c0 + tx;
            g_wt[oi] = __float2half_rn(v);
        }
    }
}

// ---- chunk staging via cp.async (256 threads, 8x16B each) -----------------------
static __device__ __forceinline__ void load_chunk(uint32_t sb, int ci,
                                                  int n, int h0, int o0, int tid)
{
    const int tap = ci >> 3;              // 0..8
    const int c0  = (ci & 7) * 64;        // kc=64
    const int dy  = tap / 3 - 1;
    const int dx  = tap % 3 - 1;
    const int r   = tid >> 1;             // 0..127
    const int cb  = (tid & 1) * 4;        // 4 consecutive 16B chunks
    const int r7  = r & 7;

    // ---- A rows (128 spatial, tap-shifted, zero-filled halo)
    int hs = h0 + (r >> 6) + dy;
    int ws = (r & 63) + dx;
    const bool ok = ((unsigned)hs < (unsigned)HH) && ((unsigned)ws < (unsigned)WW);
    const unsigned szA = ok ? 16u : 0u;
    const int hc = ok ? hs : 0;
    const int wc = ok ? ws : 0;
    const size_t aidx = ((size_t)((n * HH + hc) * WW + wc) * CC + c0 + cb * 8) * 2;
    const char* srcA = (const char*)g_xh + aidx;
#pragma unroll
    for (int c = 0; c < 4; ++c) {
        uint32_t d = sb + r * 128 + (((cb + c) ^ r7) << 4);
        CP16(d, srcA + c * 16, szA);
    }

    // ---- B rows (128 o-channels)
    const size_t bidx = ((size_t)((tap * OO + o0 + r) * CC) + c0 + cb * 8) * 2;
    const char* srcB = (const char*)g_wt + bidx;
#pragma unroll
    for (int c = 0; c < 4; ++c) {
        uint32_t d = sb + OFF_B + r * 128 + (((cb + c) ^ r7) << 4);
        CP16(d, srcB + c * 16, 16u);
    }
}

// ---- kernel 4: main conv on mma.sync, mbarrier-decoupled pipeline ----------------
__global__ __launch_bounds__(256, 2)
void conv_mma_kernel(const float* __restrict__ bias,
                     const float* __restrict__ nstr,
                     const float* __restrict__ noise,
                     float* __restrict__ out)
{
    extern __shared__ char dynsmem[];
    __shared__ __align__(8) unsigned long long s_full[3];
    __shared__ __align__(8) unsigned long long s_free[3];
    const uint32_t smbase = smem_u32(dynsmem);
    const uint32_t mb_full0 = smem_u32(&s_full[0]);
    const uint32_t mb_free0 = smem_u32(&s_free[0]);

    const int tid  = threadIdx.x;
    const int lane = tid & 31;
    const int wid  = tid >> 5;
    const int wm   = wid & 3;          // M quarter (32 rows)
    const int wn   = wid >> 2;         // N half (64 cols)

    const int o0 = blockIdx.x * 128;
    const int mt = blockIdx.y;
    const int n  = mt >> 5;
    const int h0 = (mt & 31) * 2;

    // ldmatrix lane mappings
    const int a_row  = wm * 32 + (lane & 15);            // + mi*16
    const int a_kh   = lane >> 4;
    const int bg     = lane >> 3;
    const int b_row0 = wn * 64 + ((bg >> 1) << 3) + (lane & 7);  // + nb*16
    const int b_kh   = bg & 1;

    float acc[2][8][4];
#pragma unroll
    for (int mi = 0; mi < 2; ++mi)
#pragma unroll
        for (int ni = 0; ni < 8; ++ni)
#pragma unroll
            for (int q = 0; q < 4; ++q) acc[mi][ni][q] = 0.f;

    if (tid == 0) {
#pragma unroll
        for (int s = 0; s < 3; ++s) {
            MB_INIT(mb_full0 + s * 8, 256);
            MB_INIT(mb_free0 + s * 8, 256);
        }
    }
    __syncthreads();    // publish mbarrier init (only CTA-wide barrier)

    // prologue: chunks 0 and 1 in flight, completion tracked by mbarriers
    load_chunk(smbase, 0, n, h0, o0, tid);
    CP_MB_ARRIVE(mb_full0 + 0 * 8);
    load_chunk(smbase + STAGE_BYTES, 1, n, h0, o0, tid);
    CP_MB_ARRIVE(mb_full0 + 1 * 8);

#pragma unroll 1
    for (int i = 0; i < NCHUNK; ++i) {
        const int s  = i - (i / 3) * 3;            // i % 3
        const int pf = (i / 3) & 1;                // full parity
        MB_WAIT_PAR(mb_full0 + s * 8, pf);         // chunk i data (all threads)

        const uint32_t sb = smbase + s * STAGE_BYTES;
#pragma unroll
        for (int k16 = 0; k16 < 4; ++k16) {
            const int cha = 2 * k16 + a_kh;
            const int chb = 2 * k16 + b_kh;
            uint32_t aa[2][4], bb[4][4];
#pragma unroll
            for (int mi = 0; mi < 2; ++mi)
                LDSM4(aa[mi], sb + SWZ128(a_row + mi * 16, cha));
#pragma unroll
            for (int nb = 0; nb < 4; ++nb)
                LDSM4(bb[nb], sb + OFF_B + SWZ128(b_row0 + nb * 16, chb));
#pragma unroll
            for (int mi = 0; mi < 2; ++mi)
#pragma unroll
                for (int nb = 0; nb < 4; ++nb) {
                    MMA2(acc[mi][2*nb],   aa[mi], bb[nb][0], bb[nb][1]);
                    MMA2(acc[mi][2*nb+1], aa[mi], bb[nb][2], bb[nb][3]);
                }
        }
        MB_ARRIVE(mb_free0 + s * 8);               // done reading stage s

        const int j = i + 2;                       // prefetch chunk j
        if (j < NCHUNK) {
            const int sj = j - (j / 3) * 3;        // j % 3
            if (j >= 3) {
                const int pw = ((j / 3) - 1) & 1;  // last reader: chunk j-3
                MB_WAIT_PAR(mb_free0 + sj * 8, pw);
            }
            load_chunk(smbase + sj * STAGE_BYTES, j, n, h0, o0, tid);
            CP_MB_ARRIVE(mb_full0 + sj * 8);
        }
    }

    // ---- epilogue: demod, noise, bias, leaky_relu * sqrt(2)
    const float nstrv = *nstr;
#pragma unroll
    for (int mi = 0; mi < 2; ++mi) {
#pragma unroll
        for (int half = 0; half < 2; ++half) {
            int m = wm * 32 + mi * 16 + (lane >> 2) + half * 8;
            int h = h0 + (m >> 6);
            int w = m & 63;
            float nz = noise[(n * HH + h) * WW + w] * nstrv;
            size_t base = ((size_t)((n * HH + h) * WW + w)) * OO + o0;
#pragma unroll
            for (int ni = 0; ni < 8; ++ni) {
                int oc = wn * 64 + ni * 8 + 2 * (lane & 3);
                float dm0 = g_dmul[n * OO + o0 + oc];
                float dm1 = g_dmul[n * OO + o0 + oc + 1];
                float b0 = bias[o0 + oc], b1 = bias[o0 + oc + 1];
                float y0 = fmaf(acc[mi][ni][half * 2],     dm0, nz + b0);
                float y1 = fmaf(acc[mi][ni][half * 2 + 1], dm1, nz + b1);
                y0 = (y0 > 0.f ? y0 : 0.2f * y0) * 1.4142135623730951f;
                y1 = (y1 > 0.f ? y1 : 0.2f * y1) * 1.4142135623730951f;
                *(float2*)(out + base + oc) = make_float2(y0, y1);
            }
        }
    }
}

// ---------------------------------------------------------------------------
extern "C" void kernel_launch(void* const* d_in, const int* in_sizes, int n_in,
                              void* d_out, int out_size)
{
    const float* x      = (const float*)d_in[0];
    const float* dlat   = (const float*)d_in[1];
    const float* sw     = (const float*)d_in[2];
    const float* sbv    = (const float*)d_in[3];
    const float* weight = (const float*)d_in[4];
    const float* bias   = (const float*)d_in[5];
    const float* nstr   = (const float*)d_in[6];
    const float* noise  = (const float*)d_in[7];
    const int*   lidx   = (const int*)  d_in[8];
    float* out = (float*)d_out;

    prep1_kernel<<<NN + CC, 512>>>(dlat, sw, sbv, lidx, weight);
    dmul_kernel<<<NN, 512>>>();
    prep3_kernel<<<32768 + 2304, 256>>>(x, weight);

    const int smem_bytes = 3 * STAGE_BYTES;   // 98304 per CTA (2 CTAs/SM)
    cudaFuncSetAttribute(conv_mma_kernel,
                         cudaFuncAttributeMaxDynamicSharedMemorySize, smem_bytes);
    conv_mma_kernel<<<dim3(4, 512), 256, smem_bytes>>>(bias, nstr, noise, out);
}

// round 11
// speedup vs baseline: 1.1604x; 1.1604x over previous
#include <cuda_runtime.h>
#include <cuda_fp16.h>
#include <stdint.h>

// ---------------------------------------------------------------------------
// StyleGAN2 modulated 3x3 conv, NHWC, N=16 H=W=64 C=O=512
// Round 11: R7 base (CTA 128x128, warp 32x64, kc=64, single-product fp16,
//           2 CTAs/SM) + (a) A staged ONCE per c-chunk as a zero-padded halo
//           tile reused by all 9 taps (ldmatrix per-lane row addressing),
//           (b) per-warp k16 phase rotation to desynchronize LDSM bursts.
// ---------------------------------------------------------------------------

#define NN 16
#define HH 64
#define WW 64
#define CC 512
#define OO 512
#define NWD 14

#define A_BYTES 33792        // 264 halo rows x 128B  (4x66 spatial, kc=64)
#define OFF_B0  67584        // after 2 A buffers
#define B_BYTES 16384        // 128 o-rows x 128B
#define SMEM_TOTAL (OFF_B0 + 2 * B_BYTES)   // 100352
#define NCHUNK 72            // 9 taps x 8 c-chunks

// ---- device scratch (allocation-free) --------------------------------------
__device__ float g_s[NN * CC];
__device__ float g_dmul[NN * OO];
__device__ float g_ssq[CC * OO];
__device__ __half g_xh[NN * HH * WW * CC];   // fp16(x*s)
__device__ __half g_wt[9 * OO * CC];         // fp16 w^T [tap][o][c]

// ---- helpers -----------------------------------------------------------------
static __device__ __forceinline__ uint32_t smem_u32(const void* p) {
    uint32_t a;
    asm("{ .reg .u64 t; cvta.to.shared.u64 t, %1; cvt.u32.u64 %0, t; }"
        : "=r"(a) : "l"(p));
    return a;
}

#define CP16(dst, src, sz)                                                   \
    asm volatile("cp.async.cg.shared.global [%0], [%1], 16, %2;"             \
                 :: "r"(dst), "l"(src), "r"(sz) : "memory")
#define CP_COMMIT() asm volatile("cp.async.commit_group;" ::: "memory")
#define CP_WAIT0()  asm volatile("cp.async.wait_group 0;" ::: "memory")

#define LDSM4(r, addr)                                                       \
    asm volatile("ldmatrix.sync.aligned.m8n8.x4.shared.b16 "                 \
                 "{%0,%1,%2,%3}, [%4];"                                      \
                 : "=r"((r)[0]), "=r"((r)[1]), "=r"((r)[2]), "=r"((r)[3])    \
                 : "r"(addr))

#define MMA2(d, a, b0, b1)                                                   \
    asm volatile("mma.sync.aligned.m16n8k16.row.col.f32.f16.f16.f32 "        \
                 "{%0,%1,%2,%3}, {%4,%5,%6,%7}, {%8,%9}, {%0,%1,%2,%3};"     \
                 : "+f"((d)[0]), "+f"((d)[1]), "+f"((d)[2]), "+f"((d)[3])    \
                 : "r"((a)[0]), "r"((a)[1]), "r"((a)[2]), "r"((a)[3]),       \
                   "r"(b0), "r"(b1))

// ---- prep 1: style (blocks 0..15) + ssq (blocks 16..527) ----------------------
__global__ void prep1_kernel(const float* __restrict__ dlat,
                             const float* __restrict__ sw,
                             const float* __restrict__ sb,
                             const int*   __restrict__ lidx,
                             const float* __restrict__ weight)
{
    int bid = blockIdx.x;
    int t = threadIdx.x;
    if (bid < NN) {
        int n = bid;
        __shared__ float dl[CC];
        int li = *lidx;
        dl[t] = dlat[(n * NWD + li) * CC + t];
        __syncthreads();
        float acc = 0.f;
#pragma unroll 4
        for (int w = 0; w < CC; ++w)
            acc += dl[w] * sw[w * CC + t];
        g_s[n * CC + t] = acc * 0.044194173824159216f + sb[t];
    } else {
        int i = bid - NN;
        float acc = 0.f;
#pragma unroll
        for (int tp = 0; tp < 9; ++tp) {
            float v = weight[(tp * CC + i) * OO + t];
            acc += v * v;
        }
        g_ssq[i * OO + t] = acc;
    }
}

// ---- prep 2: dmul[n,o] ---------------------------------------------------------
__global__ void dmul_kernel()
{
    int n = blockIdx.x;
    int o = threadIdx.x;
    __shared__ float s2[CC];
    float sv = g_s[n * CC + o];
    s2[o] = sv * sv;
    __syncthreads();
    float acc = 0.f;
#pragma unroll 4
    for (int i = 0; i < CC; ++i)
        acc += s2[i] * g_ssq[i * OO + o];
    const float ws2 = 1.0f / 4608.0f;
    const float ws  = 0.014731391274719738f;
    g_dmul[n * OO + o] = ws * rsqrtf(ws2 * acc + 1e-8f);
}

// ---- prep 3: x*s -> fp16 (blocks < 32768) + w transpose fp16 (rest) -------------
__global__ void prep3_kernel(const float* __restrict__ x,
                             const float* __restrict__ weight)
{
    int bid = blockIdx.x;
    int tid = threadIdx.x;
    if (bid < 32768) {
        int t = bid * 256 + tid;
        int e = t * 4;
        int c = e & (CC - 1);
        int n = e >> 21;
        float4 v = *(const float4*)(x + e);
        float4 s = *(const float4*)(g_s + n * CC + c);
        __half h0 = __float2half_rn(v.x * s.x);
        __half h1 = __float2half_rn(v.y * s.y);
        __half h2 = __float2half_rn(v.z * s.z);
        __half h3 = __float2half_rn(v.w * s.w);
        uint2 ph;
        ph.x = (uint32_t)__half_as_ushort(h0) | ((uint32_t)__half_as_ushort(h1) << 16);
        ph.y = (uint32_t)__half_as_ushort(h2) | ((uint32_t)__half_as_ushort(h3) << 16);
        *(uint2*)(g_xh + e) = ph;
    } else {
        __shared__ float ts[32][33];
        int wb = bid - 32768;            // 0..2303
        int tap = wb >> 8;
        int rem = wb & 255;
        int o0 = (rem & 15) * 32;
        int c0 = (rem >> 4) * 32;
        int tx = tid & 31, ty = tid >> 5;
        for (int j = ty; j < 32; j += 8)
            ts[j][tx] = weight[(tap * CC + c0 + j) * OO + o0 + tx];
        __syncthreads();
        for (int j = ty; j < 32; j += 8) {
            float v = ts[tx][j];
            int oi = (tap * OO + o0 + j) * CC + c0 + tx;
            g_wt[oi] = __float2half_rn(v);
        }
    }
}

// ---- A halo staging: 264 rows (4x66 spatial, zero-padded), kc=64 ----------------
static __device__ __forceinline__ void load_A(uint32_t dst, int c0,
                                              int n, int h0, int tid)
{
#pragma unroll
    for (int it = 0; it < 2; ++it) {
        int row = tid + it * 256;
        if (row < 264) {
            int rr = row >= 198 ? 3 : (row >= 132 ? 2 : (row >= 66 ? 1 : 0));
            int cc = row - rr * 66;
            int h = h0 + rr - 1;
            int w = cc - 1;
            const bool ok = ((unsigned)h < (unsigned)HH) && ((unsigned)w < (unsigned)WW);
            const unsigned sz = ok ? 16u : 0u;
            const size_t gi = ((size_t)((n * HH + (ok ? h : 0)) * WW + (ok ? w : 0)) * CC + c0) * 2;
            const char* src = (const char*)g_xh + gi;
            const int r7 = row & 7;
            const uint32_t rbase = dst + (uint32_t)row * 128u;
#pragma unroll
            for (int c = 0; c < 8; ++c)
                CP16(rbase + ((c ^ r7) << 4), src + c * 16, sz);
        }
    }
}

// ---- B staging: 128 o-rows x kc=64 ------------------------------------------------
static __device__ __forceinline__ void load_B(uint32_t dst, int tap, int c0,
                                               int o0, int tid)
{
    const int r  = tid >> 1;
    const int cb = (tid & 1) * 4;
    const int r7 = r & 7;
    const size_t bidx = ((size_t)((tap * OO + o0 + r) * CC) + c0 + cb * 8) * 2;
    const char* src = (const char*)g_wt + bidx;
    const uint32_t rbase = dst + (uint32_t)r * 128u;
#pragma unroll
    for (int c = 0; c < 4; ++c)
        CP16(rbase + (((cb + c) ^ r7) << 4), src + c * 16, 16u);
}

// ---- kernel 4: main conv on mma.sync ----------------------------------------------
__global__ __launch_bounds__(256, 2)
void conv_mma_kernel(const float* __restrict__ bias,
                     const float* __restrict__ nstr,
                     const float* __restrict__ noise,
                     float* __restrict__ out)
{
    extern __shared__ char dynsmem[];
    const uint32_t smbase = smem_u32(dynsmem);

    const int tid  = threadIdx.x;
    const int lane = tid & 31;
    const int wid  = tid >> 5;
    const int wm   = wid & 3;          // M quarter (32 rows)
    const int wn   = wid >> 2;         // N half (64 cols)

    const int o0 = blockIdx.x * 128;
    const int mt = blockIdx.y;
    const int n  = mt >> 5;
    const int h0 = (mt & 31) * 2;

    // ldmatrix lane mappings
    const int a_row  = wm * 32 + (lane & 15);
    const int a_kh   = lane >> 4;
    const int bg     = lane >> 3;
    const int b_row0 = wn * 64 + ((bg >> 1) << 3) + (lane & 7);
    const int b_kh   = bg & 1;

    // A halo per-lane row bases (pb for mi=0,1): p = pb + tapoff
    const int r0 = a_row,      r1 = a_row + 16;
    const int pb0 = (r0 >> 6) * 66 + (r0 & 63);
    const int pb1 = (r1 >> 6) * 66 + (r1 & 63);

    // B fragment row offsets within B buffer
    uint32_t bro[4], br7[4];
#pragma unroll
    for (int nb = 0; nb < 4; ++nb) {
        bro[nb] = (uint32_t)(b_row0 + nb * 16) * 128u;
        br7[nb] = (b_row0 + nb * 16) & 7;
    }

    float acc[2][8][4];
#pragma unroll
    for (int mi = 0; mi < 2; ++mi)
#pragma unroll
        for (int ni = 0; ni < 8; ++ni)
#pragma unroll
            for (int q = 0; q < 4; ++q) acc[mi][ni][q] = 0.f;

    // prologue: A(chunk 0) + B(tap 0, chunk 0)
    load_A(smbase, 0, n, h0, tid);
    load_B(smbase + OFF_B0, 0, 0, o0, tid);
    CP_COMMIT();

    int tap = 0, k = 0, tapoff = 0;
#pragma unroll 1
    for (int i = 0; i < NCHUNK; ++i) {
        CP_WAIT0();          // own copies for chunk i done
        __syncthreads();     // all visible; all finished reading bufs of i-1

        // issue loads for i+1 (B) and, mid-chunk, A for next c-chunk
        if (i + 1 < NCHUNK) {
            int tapj = tap + 1, kj = k;
            if (tapj == 9) { tapj = 0; ++kj; }
            load_B(smbase + OFF_B0 + ((i + 1) & 1) * B_BYTES, tapj, kj * 64, o0, tid);
            if (tap == 3 && k + 1 < 8)
                load_A(smbase + ((k + 1) & 1) * A_BYTES, (k + 1) * 64, n, h0, tid);
        }
        CP_COMMIT();

        const uint32_t sbA = smbase + (k & 1) * A_BYTES;
        const uint32_t sbB = smbase + OFF_B0 + (i & 1) * B_BYTES;
        const int p0 = pb0 + tapoff;
        const int p1 = pb1 + tapoff;
        const uint32_t a0b = sbA + (uint32_t)p0 * 128u;
        const uint32_t a1b = sbA + (uint32_t)p1 * 128u;
        const int p07 = p0 & 7, p17 = p1 & 7;

#pragma unroll
        for (int kk = 0; kk < 4; ++kk) {
            const int rk  = (kk + wid) & 3;          // per-warp phase rotation
            const int cha = 2 * rk + a_kh;
            const int chb = 2 * rk + b_kh;
            uint32_t aa[2][4], bb[4][4];
            LDSM4(aa[0], a0b + ((cha ^ p07) << 4));
            LDSM4(aa[1], a1b + ((cha ^ p17) << 4));
#pragma unroll
            for (int nb = 0; nb < 4; ++nb)
                LDSM4(bb[nb], sbB + bro[nb] + (((unsigned)chb ^ br7[nb]) << 4));
#pragma unroll
            for (int mi = 0; mi < 2; ++mi)
#pragma unroll
                for (int nb = 0; nb < 4; ++nb) {
                    MMA2(acc[mi][2*nb],   aa[mi], bb[nb][0], bb[nb][1]);
                    MMA2(acc[mi][2*nb+1], aa[mi], bb[nb][2], bb[nb][3]);
                }
        }

        if (++tap == 9) { tap = 0; ++k; tapoff = 0; }
        else tapoff += ((tap == 3 || tap == 6) ? 64 : 1);
    }

    // ---- epilogue: demod, noise, bias, leaky_relu * sqrt(2)
    const float nstrv = *nstr;
#pragma unroll
    for (int mi = 0; mi < 2; ++mi) {
#pragma unroll
        for (int half = 0; half < 2; ++half) {
            int m = wm * 32 + mi * 16 + (lane >> 2) + half * 8;
            int h = h0 + (m >> 6);
            int w = m & 63;
            float nz = noise[(n * HH + h) * WW + w] * nstrv;
            size_t base = ((size_t)((n * HH + h) * WW + w)) * OO + o0;
#pragma unroll
            for (int ni = 0; ni < 8; ++ni) {
                int oc = wn * 64 + ni * 8 + 2 * (lane & 3);
                float dm0 = g_dmul[n * OO + o0 + oc];
                float dm1 = g_dmul[n * OO + o0 + oc + 1];
                float b0 = bias[o0 + oc], b1 = bias[o0 + oc + 1];
                float y0 = fmaf(acc[mi][ni][half * 2],     dm0, nz + b0);
                float y1 = fmaf(acc[mi][ni][half * 2 + 1], dm1, nz + b1);
                y0 = (y0 > 0.f ? y0 : 0.2f * y0) * 1.4142135623730951f;
                y1 = (y1 > 0.f ? y1 : 0.2f * y1) * 1.4142135623730951f;
                *(float2*)(out + base + oc) = make_float2(y0, y1);
            }
        }
    }
}

// ---------------------------------------------------------------------------
extern "C" void kernel_launch(void* const* d_in, const int* in_sizes, int n_in,
                              void* d_out, int out_size)
{
    const float* x      = (const float*)d_in[0];
    const float* dlat   = (const float*)d_in[1];
    const float* sw     = (const float*)d_in[2];
    const float* sbv    = (const float*)d_in[3];
    const float* weight = (const float*)d_in[4];
    const float* bias   = (const float*)d_in[5];
    const float* nstr   = (const float*)d_in[6];
    const float* noise  = (const float*)d_in[7];
    const int*   lidx   = (const int*)  d_in[8];
    float* out = (float*)d_out;

    prep1_kernel<<<NN + CC, 512>>>(dlat, sw, sbv, lidx, weight);
    dmul_kernel<<<NN, 512>>>();
    prep3_kernel<<<32768 + 2304, 256>>>(x, weight);

    cudaFuncSetAttribute(conv_mma_kernel,
                         cudaFuncAttributeMaxDynamicSharedMemorySize, SMEM_TOTAL);
    conv_mma_kernel<<<dim3(4, 512), 256, SMEM_TOTAL>>>(bias, nstr, noise, out);
}